// round 2
// baseline (speedup 1.0000x reference)
#include <cuda_runtime.h>
#include <cstddef>

#define TSTEPS 512
#define INDIM  22
#define HDIM   64
#define NTHR   256
#define NBLK   152
#define MROW   28           // padded rows per block (real: 26 or 27)
#define KX     24           // x-part k slots (22 real + 2 zero)
#define KTOT   88           // 24 + 64

// smem floats
#define SM_W    (KTOT * 256)       // 22528  gate-interleaved weights [k][unit*4+gate]
#define SM_B    256                // interleaved bias
#define SM_ACT  (MROW * KTOT * 2)  // 4928   duplicated-pair activations [row][k] float2
#define SMEM_FLOATS (SM_W + SM_B + 2 * SM_ACT)
#define SMEM_BYTES  (SMEM_FLOATS * 4)

typedef unsigned long long ull;

__device__ __forceinline__ void ffma2(ull& d, ull a, ull b) {
    asm("fma.rn.f32x2 %0, %1, %2, %0;" : "+l"(d) : "l"(a), "l"(b));
}
__device__ __forceinline__ ull pack2(float lo, float hi) {
    ull r; asm("mov.b64 %0, {%1, %2};" : "=l"(r) : "f"(lo), "f"(hi)); return r;
}
__device__ __forceinline__ void unpack2(ull v, float& lo, float& hi) {
    asm("mov.b64 {%0, %1}, %2;" : "=f"(lo), "=f"(hi) : "l"(v));
}

__device__ __forceinline__ float sigf(float x) {
    return __fdividef(1.0f, 1.0f + __expf(-x));
}
__device__ __forceinline__ float tanh_fast(float x) {
    return __fdividef(2.0f, 1.0f + __expf(-2.0f * x)) - 1.0f;
}

__global__ __launch_bounds__(NTHR, 1)
void lstm_persistent_kernel(const float* __restrict__ in,
                            const float* __restrict__ Wih,
                            const float* __restrict__ Whh,
                            const float* __restrict__ bih,
                            const float* __restrict__ bhh,
                            float* __restrict__ out)
{
    extern __shared__ float sm[];
    float* Wsm  = sm;                 // [KTOT][256]  (unit*4+gate interleave)
    float* bsm  = Wsm + SM_W;         // [256]        interleaved
    float* act0 = bsm + SM_B;         // [MROW][KTOT] float2 dup pairs
    float* act1 = act0 + SM_ACT;

    const int tid = threadIdx.x;
    const int bid = blockIdx.x;

    // 4096 = 144*27 + 8*26
    const int M        = (bid < 144) ? 27 : 26;
    const int rowStart = (bid < 144) ? bid * 27 : 144 * 27 + (bid - 144) * 26;

    // ---- prologue: zero everything that has padding ----
    for (int i = tid; i < SM_W;       i += NTHR) Wsm[i]  = 0.0f;
    for (int i = tid; i < 2 * SM_ACT; i += NTHR) act0[i] = 0.0f;  // covers act1 too
    __syncthreads();

    // weights into gate-interleaved k-major smem
    for (int i = tid; i < 256 * INDIM; i += NTHR) {
        int gr = i / INDIM, k = i - gr * INDIM;
        int u = gr & 63, gate = gr >> 6;
        Wsm[k * 256 + u * 4 + gate] = Wih[i];
    }
    for (int i = tid; i < 256 * HDIM; i += NTHR) {
        int gr = i >> 6, k = i & 63;
        int u = gr & 63, gate = gr >> 6;
        Wsm[(KX + k) * 256 + u * 4 + gate] = Whh[i];
    }
    for (int i = tid; i < 256; i += NTHR) {
        int u = i & 63, gate = i >> 6;
        bsm[u * 4 + gate] = bih[i] + bhh[i];
    }

    // ---- x feed slots: each thread owns up to 3 scalars of the x tile ----
    const int NXL = 3;
    const float* xp[NXL];
    int  sx[NXL];           // float2 index within an act buffer
    bool xv[NXL];
#pragma unroll
    for (int q = 0; q < NXL; q++) {
        int idx = tid + q * NTHR;
        xv[q] = (idx < M * INDIM);
        int r  = idx / INDIM;
        int i2 = idx - r * INDIM;
        sx[q] = r * KTOT + i2;
        xp[q] = xv[q] ? (in + (size_t)(rowStart + r) * TSTEPS * INDIM + i2) : in;
    }

    // mapping: tx = h-unit (0..63), ty = row group (7 rows each)
    const int tx = tid & 63;
    const int ty = tid >> 6;
    const int r0 = ty * 7;

    float c[7];
#pragma unroll
    for (int r = 0; r < 7; r++) c[r] = 0.0f;

    __syncthreads();

    // x(t=0) into act0 (duplicated pairs)
#pragma unroll
    for (int q = 0; q < NXL; q++)
        if (xv[q]) { float v = xp[q][0]; ((ull*)act0)[sx[q]] = pack2(v, v); }

    const ull bif = ((const ull*)bsm)[tx * 2];
    const ull bgo = ((const ull*)bsm)[tx * 2 + 1];

    const ulonglong2* Wq = (const ulonglong2*)Wsm;
    float* outp = out + ((size_t)(rowStart + r0) * TSTEPS) * HDIM + tx;

    __syncthreads();

    // ================= main recurrence =================
    for (int t = 0; t < TSTEPS; t++) {
        const ulonglong2* A  = (const ulonglong2*)((t & 1) ? act1 : act0);
        ull*              Nx = (ull*)((t & 1) ? act0 : act1);

        // prefetch x(t+1) (global) — consumed after pointwise
        float xr[NXL];
        if (t + 1 < TSTEPS) {
#pragma unroll
            for (int q = 0; q < NXL; q++)
                xr[q] = xv[q] ? xp[q][(size_t)(t + 1) * INDIM] : 0.0f;
        }

        // ---- gates = bias + [x,h] . W  (packed f32x2, 2 gate-cols per inst) ----
        ull acc[7][2];
#pragma unroll
        for (int r = 0; r < 7; r++) { acc[r][0] = bif; acc[r][1] = bgo; }

#pragma unroll 4
        for (int k = 0; k < KTOT; k += 2) {
            ulonglong2 wA = Wq[k * 64 + tx];         // ((Wi,Wf),(Wg,Wo)) @ k
            ulonglong2 wB = Wq[(k + 1) * 64 + tx];   // @ k+1
#pragma unroll
            for (int r = 0; r < 7; r++) {
                ulonglong2 a = A[((r0 + r) * KTOT + k) >> 1];  // ((v,v)@k,(v,v)@k+1)
                ffma2(acc[r][0], a.x, wA.x);
                ffma2(acc[r][1], a.x, wA.y);
                ffma2(acc[r][0], a.y, wB.x);
                ffma2(acc[r][1], a.y, wB.y);
            }
        }

        // ---- pointwise LSTM cell, fully in registers ----
#pragma unroll
        for (int r = 0; r < 7; r++) {
            float gi, gf, gg, go;
            unpack2(acc[r][0], gi, gf);
            unpack2(acc[r][1], gg, go);
            float iv = sigf(gi);
            float fv = sigf(gf);
            float gv = tanh_fast(gg);
            float ov = sigf(go);
            float cn = fmaf(fv, c[r], iv * gv);
            c[r] = cn;
            float h = ov * tanh_fast(cn);
            Nx[(r0 + r) * KTOT + KX + tx] = pack2(h, h);   // conflict-free STS.64
            if (r0 + r < M)
                outp[(size_t)r * TSTEPS * HDIM + (size_t)t * HDIM] = h;  // coalesced over tx
        }

        // publish x(t+1) into next buffer
        if (t + 1 < TSTEPS) {
#pragma unroll
            for (int q = 0; q < NXL; q++)
                if (xv[q]) Nx[sx[q]] = pack2(xr[q], xr[q]);
        }
        __syncthreads();
    }
}

extern "C" void kernel_launch(void* const* d_in, const int* in_sizes, int n_in,
                              void* d_out, int out_size)
{
    const float* in  = (const float*)d_in[0];
    const float* Wih = (const float*)d_in[1];
    const float* Whh = (const float*)d_in[2];
    const float* bih = (const float*)d_in[3];
    const float* bhh = (const float*)d_in[4];
    float* out = (float*)d_out;

    cudaFuncSetAttribute(lstm_persistent_kernel,
                         cudaFuncAttributeMaxDynamicSharedMemorySize, SMEM_BYTES);

    lstm_persistent_kernel<<<NBLK, NTHR, SMEM_BYTES>>>(in, Wih, Whh, bih, bhh, out);
}